// round 7
// baseline (speedup 1.0000x reference)
#include <cuda_runtime.h>
#include <cstdint>

#define N_NODES 50000
#define F_DIM   64
#define N_EDGES 800000
#define TILE    256
#define HPW     65     // odd stride: conflict-free per-edge scalar LDS in hot loop

typedef unsigned long long u64;

// Scratch (static device globals -- no allocation allowed)
__device__ float g_Pa[N_NODES * F_DIM];   // feat @ W1[:64,:] + b1
__device__ float g_Pb[N_NODES * F_DIM];   // feat @ W1[64:,:]
__device__ float g_C[N_NODES];            // per-node accumulated coefficient
__device__ float g_sum;                   // sum of scores
__device__ unsigned int g_cnt;            // count(score < 0.7)
__device__ int g_idx64;                   // 1 if edge_index is int64, 0 if int32

#define FMA2(acc, a, b) asm("fma.rn.f32x2 %0, %1, %2, %0;" : "+l"(acc) : "l"(a), "l"(b))
#define PACK2(dst, lo, hi) asm("mov.b64 %0, {%1, %2};" : "=l"(dst) : "f"(lo), "f"(hi))
#define UNPACK2(lo, hi, src) asm("mov.b64 {%0, %1}, %2;" : "=f"(lo), "=f"(hi) : "l"(src))

// ---------------------------------------------------------------------------
// Detect index dtype (int64 little-endian high words are all 0 since idx<50K)
// ---------------------------------------------------------------------------
__global__ void detect_kernel(const int* __restrict__ ei32) {
    __shared__ int bad;
    if (threadIdx.x == 0) bad = 0;
    __syncthreads();
    if (ei32[2 * threadIdx.x + 1] != 0) bad = 1;   // benign race, all write 1
    __syncthreads();
    if (threadIdx.x == 0) g_idx64 = bad ? 0 : 1;
}

__global__ void zero_kernel() {
    int i = blockIdx.x * 256 + threadIdx.x;
    if (i < N_NODES) g_C[i] = 0.0f;
    if (i == 0) { g_sum = 0.0f; g_cnt = 0u; }
}

// ---------------------------------------------------------------------------
// Precompute Pa/Pb, f32x2-packed: each warp processes TWO nodes per iter.
// Lane j computes outputs j and j+32 for both nodes (packed in f32x2).
// W1 dup-packed in dynamic smem (64 KB).
// ---------------------------------------------------------------------------
struct PreSmem {
    u64 W1d[128 * 64];     // dup-packed W1
    u64 b1d[64];           // dup-packed b1
    float2 fp[8][64];      // per-warp feature pairs {fA[k], fB[k]}
};

__global__ __launch_bounds__(256, 2) void precompute_kernel(
    const float* __restrict__ feat,
    const float* __restrict__ W1,
    const float* __restrict__ b1)
{
    extern __shared__ unsigned char praw[];
    PreSmem* P = (PreSmem*)praw;
    int tid = threadIdx.x;

    for (int i = tid; i < 128 * 64; i += 256) {
        float w = W1[i];
        u64 pk; asm("mov.b64 %0, {%1, %1};" : "=l"(pk) : "f"(w));
        P->W1d[i] = pk;
    }
    if (tid < 64) {
        float bb = b1[tid];
        u64 pk; asm("mov.b64 %0, {%1, %1};" : "=l"(pk) : "f"(bb));
        P->b1d[tid] = pk;
    }
    __syncthreads();

    int warp = tid >> 5, lane = tid & 31;

    for (int pr = blockIdx.x * 8 + warp; pr < N_NODES / 2; pr += gridDim.x * 8) {
        int nA = 2 * pr, nB = 2 * pr + 1;
        float a0 = feat[nA * 64 + lane];
        float a1 = feat[nA * 64 + 32 + lane];
        float c0 = feat[nB * 64 + lane];
        float c1 = feat[nB * 64 + 32 + lane];
        P->fp[warp][lane]      = make_float2(a0, c0);
        P->fp[warp][32 + lane] = make_float2(a1, c1);
        __syncwarp();

        u64 aa = P->b1d[lane], aa2 = P->b1d[32 + lane];
        u64 ab = 0ull,         ab2 = 0ull;
#pragma unroll
        for (int k = 0; k < 64; k++) {
            u64 fk = *(const u64*)&P->fp[warp][k];
            FMA2(aa,  fk, P->W1d[k * 64 + lane]);
            FMA2(aa2, fk, P->W1d[k * 64 + 32 + lane]);
            FMA2(ab,  fk, P->W1d[(64 + k) * 64 + lane]);
            FMA2(ab2, fk, P->W1d[(64 + k) * 64 + 32 + lane]);
        }
        float lo, hi;
        UNPACK2(lo, hi, aa);  g_Pa[nA * 64 + lane]      = lo; g_Pa[nB * 64 + lane]      = hi;
        UNPACK2(lo, hi, aa2); g_Pa[nA * 64 + 32 + lane] = lo; g_Pa[nB * 64 + 32 + lane] = hi;
        UNPACK2(lo, hi, ab);  g_Pb[nA * 64 + lane]      = lo; g_Pb[nB * 64 + lane]      = hi;
        UNPACK2(lo, hi, ab2); g_Pb[nA * 64 + 32 + lane] = lo; g_Pb[nB * 64 + 32 + lane] = hi;
        __syncwarp();
    }
}

// ---------------------------------------------------------------------------
// Edge kernel: 256 edges / block, 128 threads.
//   Phase A: coalesced gather (16 lanes per edge row) -> h1 tile in smem
//   Phase B: thread (p, og) handles FOUR edges {p, p+64, p+128, p+192},
//            outputs [16*og, 16*og+16), packed fma.rn.f32x2.
//            Weight LDS amortized over 32 FMA2 (1:4).
// ---------------------------------------------------------------------------
struct EdgeSmem {
    u64 w2d[64 * 32];   // W2 dup-packed
    u64 b2d[32];
    float w3s[32];
    int ss[TILE];
    int tt[TILE];
    float4 zp[128];     // per-thread partial z for its 4 edges
    float red_v[4];
    unsigned red_c[4];
    float hp[TILE * HPW];
};

__global__ __launch_bounds__(128, 2) void edge_kernel(
    const void* __restrict__ ei_raw,
    const float* __restrict__ W2,
    const float* __restrict__ b2,
    const float* __restrict__ W3,
    const float* __restrict__ b3,
    float* __restrict__ scores)
{
    extern __shared__ unsigned char smraw[];
    EdgeSmem* S = (EdgeSmem*)smraw;
    int tid = threadIdx.x;
    int tb = blockIdx.x * TILE;

    // ---- weights ----
    for (int i = tid; i < 64 * 32; i += 128) {
        float w = W2[i];
        u64 pk; asm("mov.b64 %0, {%1, %1};" : "=l"(pk) : "f"(w));
        S->w2d[i] = pk;
    }
    if (tid < 32) {
        float bb = b2[tid];
        u64 pk; asm("mov.b64 %0, {%1, %1};" : "=l"(pk) : "f"(bb));
        S->b2d[tid] = pk;
        S->w3s[tid] = W3[tid];
    }

    // ---- edge indices ----
    {
        int idx64 = g_idx64;
#pragma unroll
        for (int i = tid; i < TILE; i += 128) {
            int e = tb + i;
            int s, t;
            if (idx64) {
                const long long* ei = (const long long*)ei_raw;
                s = (int)ei[e];
                t = (int)ei[N_EDGES + e];
            } else {
                const int* ei = (const int*)ei_raw;
                s = ei[e];
                t = ei[N_EDGES + e];
            }
            s = min(max(s, 0), N_NODES - 1);
            t = min(max(t, 0), N_NODES - 1);
            S->ss[i] = s;
            S->tt[i] = t;
        }
    }
    __syncthreads();

    // ---- Phase A: coalesced gather + relu(Pa[s]+Pb[t]) into smem ----
    {
        int grp = tid >> 4;       // 0..7
        int l16 = tid & 15;
#pragma unroll 4
        for (int r = 0; r < 32; r++) {
            int e = (r << 3) + grp;
            int s = S->ss[e];
            int t = S->tt[e];
            float4 a  = ((const float4*)(g_Pa + (size_t)s * 64))[l16];
            float4 b4 = ((const float4*)(g_Pb + (size_t)t * 64))[l16];
            float* d = S->hp + e * HPW + (l16 << 2);
            d[0] = fmaxf(a.x + b4.x, 0.0f);
            d[1] = fmaxf(a.y + b4.y, 0.0f);
            d[2] = fmaxf(a.z + b4.z, 0.0f);
            d[3] = fmaxf(a.w + b4.w, 0.0f);
        }
    }
    __syncthreads();

    // ---- Phase B ----
    int p  = tid & 63;
    int og = tid >> 6;
    const float* hA = S->hp + p * HPW;
    const float* hB = S->hp + (p + 64) * HPW;
    const float* hC = S->hp + (p + 128) * HPW;
    const float* hD = S->hp + (p + 192) * HPW;

    u64 acc0[16], acc1[16];
#pragma unroll
    for (int j = 0; j < 16; j++) {
        u64 bv = S->b2d[(og << 4) + j];
        acc0[j] = bv;
        acc1[j] = bv;
    }

#pragma unroll 4
    for (int k = 0; k < 64; k++) {
        u64 hk0, hk1;
        PACK2(hk0, hA[k], hB[k]);
        PACK2(hk1, hC[k], hD[k]);
        const ulonglong2* wr = (const ulonglong2*)(S->w2d + (k << 5) + (og << 4));
#pragma unroll
        for (int j2 = 0; j2 < 8; j2++) {
            ulonglong2 w = wr[j2];
            FMA2(acc0[2 * j2],     hk0, w.x);
            FMA2(acc0[2 * j2 + 1], hk0, w.y);
            FMA2(acc1[2 * j2],     hk1, w.x);
            FMA2(acc1[2 * j2 + 1], hk1, w.y);
        }
    }

    float zA = 0.0f, zB = 0.0f, zC = 0.0f, zD = 0.0f;
#pragma unroll
    for (int j = 0; j < 16; j++) {
        float w = S->w3s[(og << 4) + j];
        float lo, hi;
        UNPACK2(lo, hi, acc0[j]);
        zA = fmaf(fmaxf(lo, 0.0f), w, zA);
        zB = fmaf(fmaxf(hi, 0.0f), w, zB);
        UNPACK2(lo, hi, acc1[j]);
        zC = fmaf(fmaxf(lo, 0.0f), w, zC);
        zD = fmaf(fmaxf(hi, 0.0f), w, zD);
    }
    S->zp[tid] = make_float4(zA, zB, zC, zD);
    __syncthreads();

    float s0 = 0.0f, s1 = 0.0f, s2 = 0.0f, s3 = 0.0f;
    if (og == 0) {
        float b3v = __ldg(b3);
        float4 o = S->zp[tid + 64];
        s0 = 1.0f / (1.0f + expf(-(zA + o.x + b3v)));
        s1 = 1.0f / (1.0f + expf(-(zB + o.y + b3v)));
        s2 = 1.0f / (1.0f + expf(-(zC + o.z + b3v)));
        s3 = 1.0f / (1.0f + expf(-(zD + o.w + b3v)));

        scores[tb + p]       = s0;
        scores[tb + p + 64]  = s1;
        scores[tb + p + 128] = s2;
        scores[tb + p + 192] = s3;

        if (s0 < 0.7f) {
            float c = 0.05f * (1.0f - s0);
            atomicAdd(&g_C[S->ss[p]], c);
            atomicAdd(&g_C[S->tt[p]], c);
        }
        if (s1 < 0.7f) {
            float c = 0.05f * (1.0f - s1);
            atomicAdd(&g_C[S->ss[p + 64]], c);
            atomicAdd(&g_C[S->tt[p + 64]], c);
        }
        if (s2 < 0.7f) {
            float c = 0.05f * (1.0f - s2);
            atomicAdd(&g_C[S->ss[p + 128]], c);
            atomicAdd(&g_C[S->tt[p + 128]], c);
        }
        if (s3 < 0.7f) {
            float c = 0.05f * (1.0f - s3);
            atomicAdd(&g_C[S->ss[p + 192]], c);
            atomicAdd(&g_C[S->tt[p + 192]], c);
        }
    }

    // block reduction of score sum + violation count (og1 threads contribute 0)
    float v = s0 + s1 + s2 + s3;
    unsigned c = 0u;
    if (og == 0) {
        c = (unsigned)(s0 < 0.7f) + (unsigned)(s1 < 0.7f)
          + (unsigned)(s2 < 0.7f) + (unsigned)(s3 < 0.7f);
    }
#pragma unroll
    for (int o = 16; o > 0; o >>= 1) {
        v += __shfl_down_sync(0xFFFFFFFFu, v, o);
        c += __shfl_down_sync(0xFFFFFFFFu, c, o);
    }
    if ((tid & 31) == 0) { S->red_v[tid >> 5] = v; S->red_c[tid >> 5] = c; }
    __syncthreads();
    if (tid == 0) {
        v = S->red_v[0] + S->red_v[1] + S->red_v[2] + S->red_v[3];
        c = S->red_c[0] + S->red_c[1] + S->red_c[2] + S->red_c[3];
        atomicAdd(&g_sum, v);
        atomicAdd(&g_cnt, c);
    }
}

// ---------------------------------------------------------------------------
// Finalize: updated[n][f] = feat[n][f] + C[n] * tanh(feat[n][f])
// ---------------------------------------------------------------------------
__global__ __launch_bounds__(256) void finalize_kernel(
    const float* __restrict__ feat,
    float* __restrict__ out)
{
    int i = blockIdx.x * 256 + threadIdx.x;
    if (i < N_NODES * F_DIM) {
        float f = feat[i];
        float c = g_C[i >> 6];
        out[i] = fmaf(c, tanhf(f), f);
    }
    if (i == 0) {
        out[(size_t)N_NODES * F_DIM + N_EDGES]     = g_sum * (1.0f / (float)N_EDGES);
        out[(size_t)N_NODES * F_DIM + N_EDGES + 1] = (float)g_cnt;
    }
}

// ---------------------------------------------------------------------------
extern "C" void kernel_launch(void* const* d_in, const int* in_sizes, int n_in,
                              void* d_out, int out_size)
{
    const float* feat = (const float*)d_in[0];
    const void*  ei   = d_in[1];
    // d_in[2] = node_positions (unused), d_in[3] = node_radii (unused)
    const float* W1 = (const float*)d_in[4];
    const float* b1 = (const float*)d_in[5];
    const float* W2 = (const float*)d_in[6];
    const float* b2 = (const float*)d_in[7];
    const float* W3 = (const float*)d_in[8];
    const float* b3 = (const float*)d_in[9];

    float* out    = (float*)d_out;
    float* scores = out + (size_t)N_NODES * F_DIM;

    cudaFuncSetAttribute(precompute_kernel,
                         cudaFuncAttributeMaxDynamicSharedMemorySize,
                         (int)sizeof(PreSmem));
    cudaFuncSetAttribute(edge_kernel,
                         cudaFuncAttributeMaxDynamicSharedMemorySize,
                         (int)sizeof(EdgeSmem));

    detect_kernel<<<1, 512>>>((const int*)ei);
    zero_kernel<<<(N_NODES + 255) / 256, 256>>>();
    precompute_kernel<<<296, 256, sizeof(PreSmem)>>>(feat, W1, b1);
    edge_kernel<<<N_EDGES / TILE, 128, sizeof(EdgeSmem)>>>(
        ei, W2, b2, W3, b3, scores);
    finalize_kernel<<<(N_NODES * F_DIM + 255) / 256, 256>>>(feat, out);
}

// round 8
// speedup vs baseline: 1.5356x; 1.5356x over previous
#include <cuda_runtime.h>
#include <cstdint>

#define N_NODES 50000
#define F_DIM   64
#define N_EDGES 800000
#define TILE    128

typedef unsigned long long u64;
typedef unsigned int u32;

// Scratch (static device globals -- no allocation allowed)
__device__ float g_Pa[N_NODES * F_DIM];   // feat @ W1[:64,:] + b1
__device__ float g_Pb[N_NODES * F_DIM];   // feat @ W1[64:,:]
__device__ float g_C[N_NODES];            // per-node accumulated coefficient
__device__ float g_sum;                   // sum of scores
__device__ unsigned int g_cnt;            // count(score < 0.7)
__device__ int g_idx64;                   // 1 if edge_index is int64, 0 if int32

#define FMA2(acc, a, b) asm("fma.rn.f32x2 %0, %1, %2, %0;" : "+l"(acc) : "l"(a), "l"(b))
#define UNPACK2(lo, hi, src) asm("mov.b64 {%0, %1}, %2;" : "=f"(lo), "=f"(hi) : "l"(src))

// ---------------------------------------------------------------------------
// Detect index dtype (int64 little-endian high words all 0 since idx < 50K)
// ---------------------------------------------------------------------------
__global__ void detect_kernel(const int* __restrict__ ei32) {
    __shared__ int bad;
    if (threadIdx.x == 0) bad = 0;
    __syncthreads();
    if (ei32[2 * threadIdx.x + 1] != 0) bad = 1;   // benign race
    __syncthreads();
    if (threadIdx.x == 0) g_idx64 = bad ? 0 : 1;
}

__global__ void zero_kernel() {
    int i = blockIdx.x * 256 + threadIdx.x;
    if (i < N_NODES) g_C[i] = 0.0f;
    if (i == 0) { g_sum = 0.0f; g_cnt = 0u; }
}

// ---------------------------------------------------------------------------
// Precompute Pa/Pb, f32x2-packed (two nodes per warp-iteration).
// ---------------------------------------------------------------------------
struct PreSmem {
    u64 W1d[128 * 64];
    u64 b1d[64];
    float2 fp[8][64];
};

__global__ __launch_bounds__(256, 2) void precompute_kernel(
    const float* __restrict__ feat,
    const float* __restrict__ W1,
    const float* __restrict__ b1)
{
    extern __shared__ unsigned char praw[];
    PreSmem* P = (PreSmem*)praw;
    int tid = threadIdx.x;

    for (int i = tid; i < 128 * 64; i += 256) {
        float w = W1[i];
        u64 pk; asm("mov.b64 %0, {%1, %1};" : "=l"(pk) : "f"(w));
        P->W1d[i] = pk;
    }
    if (tid < 64) {
        float bb = b1[tid];
        u64 pk; asm("mov.b64 %0, {%1, %1};" : "=l"(pk) : "f"(bb));
        P->b1d[tid] = pk;
    }
    __syncthreads();

    int warp = tid >> 5, lane = tid & 31;

    for (int pr = blockIdx.x * 8 + warp; pr < N_NODES / 2; pr += gridDim.x * 8) {
        int nA = 2 * pr, nB = 2 * pr + 1;
        float a0 = feat[nA * 64 + lane];
        float a1 = feat[nA * 64 + 32 + lane];
        float c0 = feat[nB * 64 + lane];
        float c1 = feat[nB * 64 + 32 + lane];
        P->fp[warp][lane]      = make_float2(a0, c0);
        P->fp[warp][32 + lane] = make_float2(a1, c1);
        __syncwarp();

        u64 aa = P->b1d[lane], aa2 = P->b1d[32 + lane];
        u64 ab = 0ull,         ab2 = 0ull;
#pragma unroll
        for (int k = 0; k < 64; k++) {
            u64 fk = *(const u64*)&P->fp[warp][k];
            FMA2(aa,  fk, P->W1d[k * 64 + lane]);
            FMA2(aa2, fk, P->W1d[k * 64 + 32 + lane]);
            FMA2(ab,  fk, P->W1d[(64 + k) * 64 + lane]);
            FMA2(ab2, fk, P->W1d[(64 + k) * 64 + 32 + lane]);
        }
        float lo, hi;
        UNPACK2(lo, hi, aa);  g_Pa[nA * 64 + lane]      = lo; g_Pa[nB * 64 + lane]      = hi;
        UNPACK2(lo, hi, aa2); g_Pa[nA * 64 + 32 + lane] = lo; g_Pa[nB * 64 + 32 + lane] = hi;
        UNPACK2(lo, hi, ab);  g_Pb[nA * 64 + lane]      = lo; g_Pb[nB * 64 + lane]      = hi;
        UNPACK2(lo, hi, ab2); g_Pb[nA * 64 + 32 + lane] = lo; g_Pb[nB * 64 + 32 + lane] = hi;
        __syncwarp();
    }
}

// ---------------------------------------------------------------------------
// Edge kernel with tf32 mma.sync (m16n8k8).
//   Block: 128 threads (4 warps), TILE=128 edges.
//   Phase A: coalesced gather -> relu(Pa[s]+Pb[t]) scattered DIRECTLY into
//            A-fragment order (tf32) in smem (528B per 16x8 tile for banks).
//   Main:   warp w owns m-tiles {2w, 2w+1}; n=32 (4 n8-tiles); k=64 (8 steps).
//           D = h1(16x8k) x W2(8k x 8n) accumulated over 8 k-steps.
//   Epilogue: relu(h2+b2)*W3 partial per lane, quad shfl-reduce -> z,
//            sigmoid, scores, atomics.
// A-frag map (m16n8k8 tf32, row-major A):
//   a0=(r, c)  r=lane>>2, c=lane&3 ; a1=(r+8, c) ; a2=(r, c+4) ; a3=(r+8, c+4)
// B-frag (col-major B): b0=(k=lane&3, n=lane>>2) ; b1=(k+4, n)
// C:  c0=(r, 2t) c1=(r, 2t+1) c2=(r+8, 2t) c3=(r+8, 2t+1), t=lane&3
// ---------------------------------------------------------------------------
#define ATILE_BYTES 528   // 32 lanes * 16B + 16B pad (conflict spread)

struct EdgeSmem {
    char afr[64 * ATILE_BYTES];       // [mt*8+kt] tiles, 33792 B
    float bfr[4 * 8 * 32 * 2];        // [nt*8+kt][lane][2], 8192 B
    int ss[TILE], tt[TILE];
    float red_v[4];
    unsigned red_c[4];
};

__global__ __launch_bounds__(128, 4) void edge_kernel(
    const void* __restrict__ ei_raw,
    const float* __restrict__ W2,
    const float* __restrict__ b2,
    const float* __restrict__ W3,
    const float* __restrict__ b3,
    float* __restrict__ scores)
{
    __shared__ EdgeSmem S;
    int tid = threadIdx.x;
    int lane = tid & 31;
    int wid = tid >> 5;
    int tb = blockIdx.x * TILE;

    // ---- B fragments from W2 (rna-rounded tf32) ----
    for (int idx = tid; idx < 4 * 8 * 32; idx += 128) {
        int bl = idx & 31;
        int kt = (idx >> 5) & 7;
        int nt = idx >> 8;
        int kk = kt * 8 + (bl & 3);
        int nn = nt * 8 + (bl >> 2);
        float bv0 = W2[kk * 32 + nn];
        float bv1 = W2[(kk + 4) * 32 + nn];
        u32 t0, t1;
        asm("cvt.rna.tf32.f32 %0, %1;" : "=r"(t0) : "f"(bv0));
        asm("cvt.rna.tf32.f32 %0, %1;" : "=r"(t1) : "f"(bv1));
        ((u32*)S.bfr)[idx * 2]     = t0;
        ((u32*)S.bfr)[idx * 2 + 1] = t1;
    }

    // ---- edge indices (one per thread) ----
    {
        int e = tb + tid;
        int s, t;
        if (g_idx64) {
            const long long* ei = (const long long*)ei_raw;
            s = (int)ei[e];
            t = (int)ei[N_EDGES + e];
        } else {
            const int* ei = (const int*)ei_raw;
            s = ei[e];
            t = ei[N_EDGES + e];
        }
        s = min(max(s, 0), N_NODES - 1);
        t = min(max(t, 0), N_NODES - 1);
        S.ss[tid] = s;
        S.tt[tid] = t;
    }
    __syncthreads();

    // ---- Phase A: gather + relu -> A fragments (tf32) ----
    {
        int l16 = tid & 15;      // k-chunk: k = 4*l16 .. +3
        int grp = tid >> 4;      // 0..7
#pragma unroll 4
        for (int pass = 0; pass < 16; pass++) {
            int el = pass * 8 + grp;
            int s = S.ss[el];
            int t = S.tt[el];
            float4 a  = ((const float4*)(g_Pa + (size_t)s * 64))[l16];
            float4 b4 = ((const float4*)(g_Pb + (size_t)t * 64))[l16];
            float h[4];
            h[0] = fmaxf(a.x + b4.x, 0.0f);
            h[1] = fmaxf(a.y + b4.y, 0.0f);
            h[2] = fmaxf(a.z + b4.z, 0.0f);
            h[3] = fmaxf(a.w + b4.w, 0.0f);
            int mt = el >> 4;
            int r  = el & 15;
            int rb = r >> 3, r7 = r & 7;
#pragma unroll
            for (int i = 0; i < 4; i++) {
                int k  = 4 * l16 + i;
                int kt = k >> 3, kc = k & 7;
                int fl  = (r7 << 2) | (kc & 3);
                int reg = ((kc & 4) >> 1) | rb;
                u32 hv;
                asm("cvt.rna.tf32.f32 %0, %1;" : "=r"(hv) : "f"(h[i]));
                *(u32*)(S.afr + (mt * 8 + kt) * ATILE_BYTES + fl * 16 + reg * 4) = hv;
            }
        }
    }
    __syncthreads();

    // ---- MMA mainloop ----
    float c[2][4][4];
#pragma unroll
    for (int m = 0; m < 2; m++)
#pragma unroll
        for (int nt = 0; nt < 4; nt++)
#pragma unroll
            for (int q = 0; q < 4; q++) c[m][nt][q] = 0.0f;

#pragma unroll
    for (int kt = 0; kt < 8; kt++) {
        uint4 av[2];
#pragma unroll
        for (int m = 0; m < 2; m++) {
            int mt = 2 * wid + m;
            av[m] = *(const uint4*)(S.afr + (mt * 8 + kt) * ATILE_BYTES + lane * 16);
        }
#pragma unroll
        for (int nt = 0; nt < 4; nt++) {
            const u32* bp = (const u32*)S.bfr + (((nt * 8 + kt) * 32 + lane) << 1);
            u32 bv0 = bp[0], bv1 = bp[1];
#pragma unroll
            for (int m = 0; m < 2; m++) {
                asm volatile(
                    "mma.sync.aligned.m16n8k8.row.col.f32.tf32.tf32.f32 "
                    "{%0,%1,%2,%3}, {%4,%5,%6,%7}, {%8,%9}, {%0,%1,%2,%3};"
                    : "+f"(c[m][nt][0]), "+f"(c[m][nt][1]),
                      "+f"(c[m][nt][2]), "+f"(c[m][nt][3])
                    : "r"(av[m].x), "r"(av[m].y), "r"(av[m].z), "r"(av[m].w),
                      "r"(bv0), "r"(bv1));
            }
        }
    }

    // ---- Epilogue ----
    int t4 = lane & 3, g4 = lane >> 2;
    float b2r[4][2], w3r[4][2];
#pragma unroll
    for (int nt = 0; nt < 4; nt++) {
        int j = nt * 8 + 2 * t4;
        b2r[nt][0] = __ldg(b2 + j);
        b2r[nt][1] = __ldg(b2 + j + 1);
        w3r[nt][0] = __ldg(W3 + j);
        w3r[nt][1] = __ldg(W3 + j + 1);
    }
    float b3v = __ldg(b3);
    float vsum = 0.0f;
    unsigned vcnt = 0u;

#pragma unroll
    for (int m = 0; m < 2; m++) {
        float zlo = 0.0f, zhi = 0.0f;
#pragma unroll
        for (int nt = 0; nt < 4; nt++) {
            zlo += fmaxf(c[m][nt][0] + b2r[nt][0], 0.0f) * w3r[nt][0]
                 + fmaxf(c[m][nt][1] + b2r[nt][1], 0.0f) * w3r[nt][1];
            zhi += fmaxf(c[m][nt][2] + b2r[nt][0], 0.0f) * w3r[nt][0]
                 + fmaxf(c[m][nt][3] + b2r[nt][1], 0.0f) * w3r[nt][1];
        }
        zlo += __shfl_xor_sync(0xFFFFFFFFu, zlo, 1);
        zlo += __shfl_xor_sync(0xFFFFFFFFu, zlo, 2);
        zhi += __shfl_xor_sync(0xFFFFFFFFu, zhi, 1);
        zhi += __shfl_xor_sync(0xFFFFFFFFu, zhi, 2);

        if (t4 == 0) {
            int el1 = wid * 32 + m * 16 + g4;
            int el2 = el1 + 8;
            float s1 = 1.0f / (1.0f + expf(-(zlo + b3v)));
            float s2 = 1.0f / (1.0f + expf(-(zhi + b3v)));
            scores[tb + el1] = s1;
            scores[tb + el2] = s2;
            vsum += s1 + s2;
            if (s1 < 0.7f) {
                vcnt++;
                float cf = 0.05f * (1.0f - s1);
                atomicAdd(&g_C[S.ss[el1]], cf);
                atomicAdd(&g_C[S.tt[el1]], cf);
            }
            if (s2 < 0.7f) {
                vcnt++;
                float cf = 0.05f * (1.0f - s2);
                atomicAdd(&g_C[S.ss[el2]], cf);
                atomicAdd(&g_C[S.tt[el2]], cf);
            }
        }
    }

    // ---- block reduction of score sum + violation count ----
#pragma unroll
    for (int o = 16; o > 0; o >>= 1) {
        vsum += __shfl_down_sync(0xFFFFFFFFu, vsum, o);
        vcnt += __shfl_down_sync(0xFFFFFFFFu, vcnt, o);
    }
    if (lane == 0) { S.red_v[wid] = vsum; S.red_c[wid] = vcnt; }
    __syncthreads();
    if (tid == 0) {
        float v = S.red_v[0] + S.red_v[1] + S.red_v[2] + S.red_v[3];
        unsigned cc = S.red_c[0] + S.red_c[1] + S.red_c[2] + S.red_c[3];
        atomicAdd(&g_sum, v);
        atomicAdd(&g_cnt, cc);
    }
}

// ---------------------------------------------------------------------------
// Finalize: updated[n][f] = feat[n][f] + C[n] * tanh(feat[n][f])
// ---------------------------------------------------------------------------
__global__ __launch_bounds__(256) void finalize_kernel(
    const float* __restrict__ feat,
    float* __restrict__ out)
{
    int i = blockIdx.x * 256 + threadIdx.x;
    if (i < N_NODES * F_DIM) {
        float f = feat[i];
        float cc = g_C[i >> 6];
        out[i] = fmaf(cc, tanhf(f), f);
    }
    if (i == 0) {
        out[(size_t)N_NODES * F_DIM + N_EDGES]     = g_sum * (1.0f / (float)N_EDGES);
        out[(size_t)N_NODES * F_DIM + N_EDGES + 1] = (float)g_cnt;
    }
}

// ---------------------------------------------------------------------------
extern "C" void kernel_launch(void* const* d_in, const int* in_sizes, int n_in,
                              void* d_out, int out_size)
{
    const float* feat = (const float*)d_in[0];
    const void*  ei   = d_in[1];
    // d_in[2] = node_positions (unused), d_in[3] = node_radii (unused)
    const float* W1 = (const float*)d_in[4];
    const float* b1 = (const float*)d_in[5];
    const float* W2 = (const float*)d_in[6];
    const float* b2 = (const float*)d_in[7];
    const float* W3 = (const float*)d_in[8];
    const float* b3 = (const float*)d_in[9];

    float* out    = (float*)d_out;
    float* scores = out + (size_t)N_NODES * F_DIM;

    cudaFuncSetAttribute(precompute_kernel,
                         cudaFuncAttributeMaxDynamicSharedMemorySize,
                         (int)sizeof(PreSmem));

    detect_kernel<<<1, 512>>>((const int*)ei);
    zero_kernel<<<(N_NODES + 255) / 256, 256>>>();
    precompute_kernel<<<296, 256, sizeof(PreSmem)>>>(feat, W1, b1);
    edge_kernel<<<N_EDGES / TILE, 128>>>(ei, W2, b2, W3, b3, scores);
    finalize_kernel<<<(N_NODES * F_DIM + 255) / 256, 256>>>(feat, out);
}

// round 10
// speedup vs baseline: 1.6267x; 1.0593x over previous
#include <cuda_runtime.h>
#include <cstdint>

#define N_NODES 50000
#define F_DIM   64
#define N_EDGES 800000
#define TILE    256

typedef unsigned long long u64;
typedef unsigned int u32;

// Scratch (static device globals -- no allocation allowed)
__device__ float g_Pa[N_NODES * F_DIM];   // feat @ W1[:64,:] + b1
__device__ float g_Pb[N_NODES * F_DIM];   // feat @ W1[64:,:]
__device__ float g_C[N_NODES];            // per-node accumulated coefficient
__device__ float g_sum;                   // sum of scores
__device__ unsigned int g_cnt;            // count(score < 0.7)
__device__ int g_idx64;                   // 1 if edge_index is int64, 0 if int32

#define FMA2(acc, a, b) asm("fma.rn.f32x2 %0, %1, %2, %0;" : "+l"(acc) : "l"(a), "l"(b))
#define UNPACK2(lo, hi, src) asm("mov.b64 {%0, %1}, %2;" : "=f"(lo), "=f"(hi) : "l"(src))

// ---------------------------------------------------------------------------
__global__ void detect_kernel(const int* __restrict__ ei32) {
    __shared__ int bad;
    if (threadIdx.x == 0) bad = 0;
    __syncthreads();
    if (ei32[2 * threadIdx.x + 1] != 0) bad = 1;   // benign race
    __syncthreads();
    if (threadIdx.x == 0) g_idx64 = bad ? 0 : 1;
}

__global__ void zero_kernel() {
    int i = blockIdx.x * 256 + threadIdx.x;
    if (i < N_NODES) g_C[i] = 0.0f;
    if (i == 0) { g_sum = 0.0f; g_cnt = 0u; }
}

// ---------------------------------------------------------------------------
// Precompute Pa/Pb, f32x2-packed (two nodes per warp-iteration).
// ---------------------------------------------------------------------------
struct PreSmem {
    u64 W1d[128 * 64];
    u64 b1d[64];
    float2 fp[8][64];
};

__global__ __launch_bounds__(256, 2) void precompute_kernel(
    const float* __restrict__ feat,
    const float* __restrict__ W1,
    const float* __restrict__ b1)
{
    extern __shared__ unsigned char praw[];
    PreSmem* P = (PreSmem*)praw;
    int tid = threadIdx.x;

    for (int i = tid; i < 128 * 64; i += 256) {
        float w = W1[i];
        u64 pk; asm("mov.b64 %0, {%1, %1};" : "=l"(pk) : "f"(w));
        P->W1d[i] = pk;
    }
    if (tid < 64) {
        float bb = b1[tid];
        u64 pk; asm("mov.b64 %0, {%1, %1};" : "=l"(pk) : "f"(bb));
        P->b1d[tid] = pk;
    }
    __syncthreads();

    int warp = tid >> 5, lane = tid & 31;

    for (int pr = blockIdx.x * 8 + warp; pr < N_NODES / 2; pr += gridDim.x * 8) {
        int nA = 2 * pr, nB = 2 * pr + 1;
        float a0 = feat[nA * 64 + lane];
        float a1 = feat[nA * 64 + 32 + lane];
        float c0 = feat[nB * 64 + lane];
        float c1 = feat[nB * 64 + 32 + lane];
        P->fp[warp][lane]      = make_float2(a0, c0);
        P->fp[warp][32 + lane] = make_float2(a1, c1);
        __syncwarp();

        u64 aa = P->b1d[lane], aa2 = P->b1d[32 + lane];
        u64 ab = 0ull,         ab2 = 0ull;
#pragma unroll
        for (int k = 0; k < 64; k++) {
            u64 fk = *(const u64*)&P->fp[warp][k];
            FMA2(aa,  fk, P->W1d[k * 64 + lane]);
            FMA2(aa2, fk, P->W1d[k * 64 + 32 + lane]);
            FMA2(ab,  fk, P->W1d[(64 + k) * 64 + lane]);
            FMA2(ab2, fk, P->W1d[(64 + k) * 64 + 32 + lane]);
        }
        float lo, hi;
        UNPACK2(lo, hi, aa);  g_Pa[nA * 64 + lane]      = lo; g_Pa[nB * 64 + lane]      = hi;
        UNPACK2(lo, hi, aa2); g_Pa[nA * 64 + 32 + lane] = lo; g_Pa[nB * 64 + 32 + lane] = hi;
        UNPACK2(lo, hi, ab);  g_Pb[nA * 64 + lane]      = lo; g_Pb[nB * 64 + lane]      = hi;
        UNPACK2(lo, hi, ab2); g_Pb[nA * 64 + 32 + lane] = lo; g_Pb[nB * 64 + 32 + lane] = hi;
        __syncwarp();
    }
}

// ---------------------------------------------------------------------------
// Edge kernel with tf32 mma.sync (m16n8k8).  TILE=256, 256 threads, 8 warps.
// A-values stored as raw f32 bits (hardware truncates to tf32).
// ---------------------------------------------------------------------------
#define ATILE_BYTES 528

struct EdgeSmem {
    char afr[128 * ATILE_BYTES];      // 16 m-tiles x 8 k-tiles, 67584 B
    float bfr[4 * 8 * 32 * 2];        // [nt*8+kt][lane][2], 8192 B
    int ss[TILE], tt[TILE];
    float red_v[8];
    unsigned red_c[8];
};

__global__ __launch_bounds__(256, 2) void edge_kernel(
    const void* __restrict__ ei_raw,
    const float* __restrict__ W2,
    const float* __restrict__ b2,
    const float* __restrict__ W3,
    const float* __restrict__ b3,
    float* __restrict__ scores)
{
    extern __shared__ unsigned char smraw[];
    EdgeSmem& S = *(EdgeSmem*)smraw;
    int tid = threadIdx.x;
    int lane = tid & 31;
    int wid = tid >> 5;
    int tb = blockIdx.x * TILE;

    // ---- B fragments from W2 (rna-rounded tf32; cheap, per-CTA) ----
    for (int idx = tid; idx < 4 * 8 * 32; idx += 256) {
        int bl = idx & 31;
        int kt = (idx >> 5) & 7;
        int nt = idx >> 8;
        int kk = kt * 8 + (bl & 3);
        int nn = nt * 8 + (bl >> 2);
        float bv0 = W2[kk * 32 + nn];
        float bv1 = W2[(kk + 4) * 32 + nn];
        u32 t0, t1;
        asm("cvt.rna.tf32.f32 %0, %1;" : "=r"(t0) : "f"(bv0));
        asm("cvt.rna.tf32.f32 %0, %1;" : "=r"(t1) : "f"(bv1));
        ((u32*)S.bfr)[idx * 2]     = t0;
        ((u32*)S.bfr)[idx * 2 + 1] = t1;
    }

    // ---- edge indices (one per thread) ----
    {
        int e = tb + tid;
        int s, t;
        if (g_idx64) {
            const long long* ei = (const long long*)ei_raw;
            s = (int)ei[e];
            t = (int)ei[N_EDGES + e];
        } else {
            const int* ei = (const int*)ei_raw;
            s = ei[e];
            t = ei[N_EDGES + e];
        }
        s = min(max(s, 0), N_NODES - 1);
        t = min(max(t, 0), N_NODES - 1);
        S.ss[tid] = s;
        S.tt[tid] = t;
    }
    __syncthreads();

    // ---- Phase A: gather + relu -> A fragments (raw f32 bits as tf32) ----
    {
        int l16 = tid & 15;      // k-chunk: k = 4*l16 .. +3
        int grp = tid >> 4;      // 0..15
#pragma unroll 4
        for (int pass = 0; pass < 16; pass++) {
            int el = pass * 16 + grp;
            int s = S.ss[el];
            int t = S.tt[el];
            float4 a  = ((const float4*)(g_Pa + (size_t)s * 64))[l16];
            float4 b4 = ((const float4*)(g_Pb + (size_t)t * 64))[l16];
            float h[4];
            h[0] = fmaxf(a.x + b4.x, 0.0f);
            h[1] = fmaxf(a.y + b4.y, 0.0f);
            h[2] = fmaxf(a.z + b4.z, 0.0f);
            h[3] = fmaxf(a.w + b4.w, 0.0f);
            int mt = el >> 4;
            int r  = el & 15;
            int rb = r >> 3, r7 = r & 7;
#pragma unroll
            for (int i = 0; i < 4; i++) {
                int k  = 4 * l16 + i;
                int kt = k >> 3, kc = k & 7;
                int fl  = (r7 << 2) | (kc & 3);
                int reg = ((kc & 4) >> 1) | rb;
                *(u32*)(S.afr + (mt * 8 + kt) * ATILE_BYTES + fl * 16 + reg * 4)
                    = __float_as_uint(h[i]);
            }
        }
    }
    __syncthreads();

    // ---- MMA mainloop: warp owns m-tiles {2w, 2w+1} ----
    float c[2][4][4];
#pragma unroll
    for (int m = 0; m < 2; m++)
#pragma unroll
        for (int nt = 0; nt < 4; nt++)
#pragma unroll
            for (int q = 0; q < 4; q++) c[m][nt][q] = 0.0f;

#pragma unroll
    for (int kt = 0; kt < 8; kt++) {
        uint4 av[2];
#pragma unroll
        for (int m = 0; m < 2; m++) {
            int mt = 2 * wid + m;
            av[m] = *(const uint4*)(S.afr + (mt * 8 + kt) * ATILE_BYTES + lane * 16);
        }
#pragma unroll
        for (int nt = 0; nt < 4; nt++) {
            const u32* bp = (const u32*)S.bfr + (((nt * 8 + kt) * 32 + lane) << 1);
            u32 bv0 = bp[0], bv1 = bp[1];
#pragma unroll
            for (int m = 0; m < 2; m++) {
                asm volatile(
                    "mma.sync.aligned.m16n8k8.row.col.f32.tf32.tf32.f32 "
                    "{%0,%1,%2,%3}, {%4,%5,%6,%7}, {%8,%9}, {%0,%1,%2,%3};"
                    : "+f"(c[m][nt][0]), "+f"(c[m][nt][1]),
                      "+f"(c[m][nt][2]), "+f"(c[m][nt][3])
                    : "r"(av[m].x), "r"(av[m].y), "r"(av[m].z), "r"(av[m].w),
                      "r"(bv0), "r"(bv1));
            }
        }
    }

    // ---- Epilogue ----
    int t4 = lane & 3, g4 = lane >> 2;
    float b2r[4][2], w3r[4][2];
#pragma unroll
    for (int nt = 0; nt < 4; nt++) {
        int j = nt * 8 + 2 * t4;
        b2r[nt][0] = __ldg(b2 + j);
        b2r[nt][1] = __ldg(b2 + j + 1);
        w3r[nt][0] = __ldg(W3 + j);
        w3r[nt][1] = __ldg(W3 + j + 1);
    }
    float b3v = __ldg(b3);
    float vsum = 0.0f;
    unsigned vcnt = 0u;

#pragma unroll
    for (int m = 0; m < 2; m++) {
        float zlo = 0.0f, zhi = 0.0f;
#pragma unroll
        for (int nt = 0; nt < 4; nt++) {
            zlo += fmaxf(c[m][nt][0] + b2r[nt][0], 0.0f) * w3r[nt][0]
                 + fmaxf(c[m][nt][1] + b2r[nt][1], 0.0f) * w3r[nt][1];
            zhi += fmaxf(c[m][nt][2] + b2r[nt][0], 0.0f) * w3r[nt][0]
                 + fmaxf(c[m][nt][3] + b2r[nt][1], 0.0f) * w3r[nt][1];
        }
        zlo += __shfl_xor_sync(0xFFFFFFFFu, zlo, 1);
        zlo += __shfl_xor_sync(0xFFFFFFFFu, zlo, 2);
        zhi += __shfl_xor_sync(0xFFFFFFFFu, zhi, 1);
        zhi += __shfl_xor_sync(0xFFFFFFFFu, zhi, 2);

        if (t4 == 0) {
            int el1 = wid * 32 + m * 16 + g4;
            int el2 = el1 + 8;
            float s1 = 1.0f / (1.0f + __expf(-(zlo + b3v)));
            float s2 = 1.0f / (1.0f + __expf(-(zhi + b3v)));
            scores[tb + el1] = s1;
            scores[tb + el2] = s2;
            vsum += s1 + s2;
            if (s1 < 0.7f) {
                vcnt++;
                float cf = 0.05f * (1.0f - s1);
                atomicAdd(&g_C[S.ss[el1]], cf);
                atomicAdd(&g_C[S.tt[el1]], cf);
            }
            if (s2 < 0.7f) {
                vcnt++;
                float cf = 0.05f * (1.0f - s2);
                atomicAdd(&g_C[S.ss[el2]], cf);
                atomicAdd(&g_C[S.tt[el2]], cf);
            }
        }
    }

    // ---- block reduction ----
#pragma unroll
    for (int o = 16; o > 0; o >>= 1) {
        vsum += __shfl_down_sync(0xFFFFFFFFu, vsum, o);
        vcnt += __shfl_down_sync(0xFFFFFFFFu, vcnt, o);
    }
    if (lane == 0) { S.red_v[wid] = vsum; S.red_c[wid] = vcnt; }
    __syncthreads();
    if (tid == 0) {
        float v = 0.0f; unsigned cc = 0u;
#pragma unroll
        for (int w = 0; w < 8; w++) { v += S.red_v[w]; cc += S.red_c[w]; }
        atomicAdd(&g_sum, v);
        atomicAdd(&g_cnt, cc);
    }
}

// ---------------------------------------------------------------------------
// Finalize with tanh.approx.f32
// ---------------------------------------------------------------------------
__global__ __launch_bounds__(256) void finalize_kernel(
    const float* __restrict__ feat,
    float* __restrict__ out)
{
    int i = blockIdx.x * 256 + threadIdx.x;
    if (i < N_NODES * F_DIM) {
        float f = feat[i];
        float cc = g_C[i >> 6];
        float th;
        asm("tanh.approx.f32 %0, %1;" : "=f"(th) : "f"(f));
        out[i] = fmaf(cc, th, f);
    }
    if (i == 0) {
        out[(size_t)N_NODES * F_DIM + N_EDGES]     = g_sum * (1.0f / (float)N_EDGES);
        out[(size_t)N_NODES * F_DIM + N_EDGES + 1] = (float)g_cnt;
    }
}

// ---------------------------------------------------------------------------
extern "C" void kernel_launch(void* const* d_in, const int* in_sizes, int n_in,
                              void* d_out, int out_size)
{
    const float* feat = (const float*)d_in[0];
    const void*  ei   = d_in[1];
    // d_in[2] = node_positions (unused), d_in[3] = node_radii (unused)
    const float* W1 = (const float*)d_in[4];
    const float* b1 = (const float*)d_in[5];
    const float* W2 = (const float*)d_in[6];
    const float* b2 = (const float*)d_in[7];
    const float* W3 = (const float*)d_in[8];
    const float* b3 = (const float*)d_in[9];

    float* out    = (float*)d_out;
    float* scores = out + (size_t)N_NODES * F_DIM;

    cudaFuncSetAttribute(precompute_kernel,
                         cudaFuncAttributeMaxDynamicSharedMemorySize,
                         (int)sizeof(PreSmem));
    cudaFuncSetAttribute(edge_kernel,
                         cudaFuncAttributeMaxDynamicSharedMemorySize,
                         (int)sizeof(EdgeSmem));

    detect_kernel<<<1, 512>>>((const int*)ei);
    zero_kernel<<<(N_NODES + 255) / 256, 256>>>();
    precompute_kernel<<<296, 256, sizeof(PreSmem)>>>(feat, W1, b1);
    edge_kernel<<<N_EDGES / TILE, 256, sizeof(EdgeSmem)>>>(
        ei, W2, b2, W3, b3, scores);
    finalize_kernel<<<(N_NODES * F_DIM + 255) / 256, 256>>>(feat, out);
}